// round 14
// baseline (speedup 1.0000x reference)
#include <cuda_runtime.h>
#include <math.h>

#define VOCAB 50000
#define D 300
#define S 5
#define CTX 10
#define B 16384
#define XCOLS (2 + CTX)

#define WPE 3                     // warps per batch element (25 float4 each)
#define THREADS 256
#define TOTWARPS (B * WPE)        // 49152 warps
#define NBLOCKS (TOTWARPS * 32 / THREADS)   // 6144 blocks

// Zero at module load; finalize resets after each read -> graph-replay safe.
__device__ float g_acc[S];

__global__ __launch_bounds__(THREADS) void sense_main_kernel(
    const int* __restrict__ x,
    const float* __restrict__ Wg,
    const float* __restrict__ Ws)
{
    const int gwarp = (blockIdx.x * THREADS + threadIdx.x) >> 5;
    const int lane  = threadIdx.x & 31;
    const int elem  = gwarp / WPE;
    const int chunk = gwarp - elem * WPE;

    __shared__ float ssum[S];
    if (threadIdx.x < S) ssum[threadIdx.x] = 0.0f;
    __syncthreads();

    float p[S] = {0.f, 0.f, 0.f, 0.f, 0.f};

    {
        // x row is 12 ints = 48 B, 16B-aligned -> 3 int4 loads.
        const int4* xq = (const int4*)(x + (size_t)elem * XCOLS);
        const int4 q0 = __ldg(&xq[0]);   // x0, x1, c0, c1
        const int4 q1 = __ldg(&xq[1]);   // c2..c5
        const int4 q2 = __ldg(&xq[2]);   // c6..c9
        const int x0 = q0.x;
        const int w[CTX] = {q0.z, q0.w, q1.x, q1.y, q1.z, q1.w, q2.x, q2.y, q2.z, q2.w};

        // This warp's 25 float4 slice of every row: indices [chunk*25, chunk*25+25).
        const int off = chunk * 25 + lane;
        const bool act = (lane < 25);             // 75 float4 per 300-float row

        // The warp's ENTIRE load set: 15 independent LDG.128s. Nothing below
        // can start until they land, so ptxas must front-batch all of them.
        float4 tg[CTX];
        #pragma unroll
        for (int j = 0; j < CTX; j++)
            tg[j] = act ? ((const float4*)(Wg + (size_t)w[j] * D))[off]
                        : make_float4(0.f, 0.f, 0.f, 0.f);
        float4 ts[S];
        #pragma unroll
        for (int s = 0; s < S; s++)
            ts[s] = act ? ((const float4*)(Ws + ((size_t)x0 * S + s) * D))[off]
                        : make_float4(0.f, 0.f, 0.f, 0.f);

        float4 ctx = tg[0];
        #pragma unroll
        for (int j = 1; j < CTX; j++) {
            ctx.x += tg[j].x; ctx.y += tg[j].y;
            ctx.z += tg[j].z; ctx.w += tg[j].w;
        }
        #pragma unroll
        for (int s = 0; s < S; s++)
            p[s] = ts[s].x * ctx.x + ts[s].y * ctx.y
                 + ts[s].z * ctx.z + ts[s].w * ctx.w;
    }

    // warp reduce each sense partial
    #pragma unroll
    for (int s = 0; s < S; s++) {
        float v = p[s];
        #pragma unroll
        for (int o = 16; o > 0; o >>= 1)
            v += __shfl_xor_sync(0xFFFFFFFFu, v, o);
        p[s] = v;
    }

    // block combine via shared atomics (8 warps x 5)
    if (lane == 0) {
        #pragma unroll
        for (int s = 0; s < S; s++)
            atomicAdd(&ssum[s], p[s]);
    }
    __syncthreads();

    // one global atomicAdd per block per sense (30720 total to 5 addresses,
    // overlapped with the memory-bound bulk)
    if (threadIdx.x < S)
        atomicAdd(&g_acc[threadIdx.x], ssum[threadIdx.x]);
}

__global__ void finalize_kernel(float* __restrict__ out) {
    // PDL: launches while sense_main_kernel drains; blocks until the primary
    // grid's memory ops (g_acc atomics) are visible.
    cudaGridDependencySynchronize();
    if (threadIdx.x < S) {
        float v = g_acc[threadIdx.x];
        out[threadIdx.x] = 1.0f / (1.0f + expf(-v));
        g_acc[threadIdx.x] = 0.0f;   // reset for next call / graph replay
    }
}

extern "C" void kernel_launch(void* const* d_in, const int* in_sizes, int n_in,
                              void* d_out, int out_size) {
    const int*   x  = (const int*)d_in[0];
    const float* Wg = (const float*)d_in[1];
    const float* Ws = (const float*)d_in[2];
    float* out = (float*)d_out;

    sense_main_kernel<<<NBLOCKS, THREADS>>>(x, Wg, Ws);

    cudaLaunchAttribute attrs[1];
    attrs[0].id = cudaLaunchAttributeProgrammaticStreamSerialization;
    attrs[0].val.programmaticStreamSerializationAllowed = 1;

    cudaLaunchConfig_t cfg = {};
    cfg.gridDim = dim3(1, 1, 1);
    cfg.blockDim = dim3(32, 1, 1);
    cfg.dynamicSmemBytes = 0;
    cfg.stream = 0;
    cfg.attrs = attrs;
    cfg.numAttrs = 1;

    cudaLaunchKernelEx(&cfg, finalize_kernel, out);
}

// round 15
// speedup vs baseline: 1.1170x; 1.1170x over previous
#include <cuda_runtime.h>
#include <math.h>

#define VOCAB 50000
#define D 300
#define S 5
#define CTX 10
#define B 16384
#define XCOLS (2 + CTX)

#define F4 75                     // float4 chunks per 300-float row
#define THREADS 256
#define NTASKS (B * F4)           // 1,228,800 lane-tasks
#define NBLOCKS (NTASKS / THREADS) // 4800 blocks

// Zero at module load; finalize resets after each read -> graph-replay safe.
__device__ float g_acc[S];

__global__ __launch_bounds__(THREADS) void sense_main_kernel(
    const int* __restrict__ x,
    const float* __restrict__ Wg,
    const float* __restrict__ Ws)
{
    const int g    = blockIdx.x * THREADS + threadIdx.x;   // task id
    const int elem = g / F4;                               // const-div -> mul.hi
    const int f    = g - elem * F4;                        // float4 index in row
    const int lane = threadIdx.x & 31;

    __shared__ float ssum[S];
    if (threadIdx.x < S) ssum[threadIdx.x] = 0.0f;
    __syncthreads();

    float p[S];

    {
        // x row is 12 ints = 48 B, 16B-aligned -> 3 int4 loads.
        // Neighboring lanes share the element -> broadcast/L1 hits.
        const int4* xq = (const int4*)(x + (size_t)elem * XCOLS);
        const int4 q0 = __ldg(&xq[0]);   // x0, x1, c0, c1
        const int4 q1 = __ldg(&xq[1]);   // c2..c5
        const int4 q2 = __ldg(&xq[2]);   // c6..c9
        const int x0 = q0.x;
        const int w[CTX] = {q0.z, q0.w, q1.x, q1.y, q1.z, q1.w, q2.x, q2.y, q2.z, q2.w};

        // 15 fully independent LDG.128s per thread; every lane active.
        float4 tg[CTX];
        #pragma unroll
        for (int j = 0; j < CTX; j++)
            tg[j] = ((const float4*)(Wg + (size_t)w[j] * D))[f];
        float4 ts[S];
        #pragma unroll
        for (int s = 0; s < S; s++)
            ts[s] = ((const float4*)(Ws + ((size_t)x0 * S + s) * D))[f];

        float4 ctx = tg[0];
        #pragma unroll
        for (int j = 1; j < CTX; j++) {
            ctx.x += tg[j].x; ctx.y += tg[j].y;
            ctx.z += tg[j].z; ctx.w += tg[j].w;
        }
        #pragma unroll
        for (int s = 0; s < S; s++)
            p[s] = ts[s].x * ctx.x + ts[s].y * ctx.y
                 + ts[s].z * ctx.z + ts[s].w * ctx.w;
    }

    // warp reduce each sense partial (cross-element mixing is fine: the
    // output sums over the whole batch)
    #pragma unroll
    for (int s = 0; s < S; s++) {
        float v = p[s];
        #pragma unroll
        for (int o = 16; o > 0; o >>= 1)
            v += __shfl_xor_sync(0xFFFFFFFFu, v, o);
        p[s] = v;
    }

    // block combine via shared atomics (8 warps x 5)
    if (lane == 0) {
        #pragma unroll
        for (int s = 0; s < S; s++)
            atomicAdd(&ssum[s], p[s]);
    }
    __syncthreads();

    // one global atomicAdd per block per sense (24000 total to 5 addresses,
    // overlapped with the memory-bound bulk)
    if (threadIdx.x < S)
        atomicAdd(&g_acc[threadIdx.x], ssum[threadIdx.x]);
}

__global__ void finalize_kernel(float* __restrict__ out) {
    // PDL: launches while sense_main_kernel drains; blocks until the primary
    // grid's memory ops (g_acc atomics) are visible.
    cudaGridDependencySynchronize();
    if (threadIdx.x < S) {
        float v = g_acc[threadIdx.x];
        out[threadIdx.x] = 1.0f / (1.0f + expf(-v));
        g_acc[threadIdx.x] = 0.0f;   // reset for next call / graph replay
    }
}

extern "C" void kernel_launch(void* const* d_in, const int* in_sizes, int n_in,
                              void* d_out, int out_size) {
    const int*   x  = (const int*)d_in[0];
    const float* Wg = (const float*)d_in[1];
    const float* Ws = (const float*)d_in[2];
    float* out = (float*)d_out;

    sense_main_kernel<<<NBLOCKS, THREADS>>>(x, Wg, Ws);

    cudaLaunchAttribute attrs[1];
    attrs[0].id = cudaLaunchAttributeProgrammaticStreamSerialization;
    attrs[0].val.programmaticStreamSerializationAllowed = 1;

    cudaLaunchConfig_t cfg = {};
    cfg.gridDim = dim3(1, 1, 1);
    cfg.blockDim = dim3(32, 1, 1);
    cfg.dynamicSmemBytes = 0;
    cfg.stream = 0;
    cfg.attrs = attrs;
    cfg.numAttrs = 1;

    cudaLaunchKernelEx(&cfg, finalize_kernel, out);
}

// round 16
// speedup vs baseline: 1.1846x; 1.0606x over previous
#include <cuda_runtime.h>
#include <math.h>

#define VOCAB 50000
#define D 300
#define S 5
#define CTX 10
#define B 16384
#define XCOLS (2 + CTX)

#define F4 75                     // float4 chunks per 300-float row
#define THREADS 256
#define NTASKS (B * F4)           // 1,228,800 lane-tasks
#define NBLOCKS (NTASKS / THREADS) // 4800 blocks

// Zero at module load; finalize resets after each read -> graph-replay safe.
__device__ float g_acc[S];

__global__ __launch_bounds__(THREADS) void sense_main_kernel(
    const int* __restrict__ x,
    const float* __restrict__ Wg,
    const float* __restrict__ Ws)
{
    // PDL trigger at CTA entry: once every CTA has executed this, the
    // dependent finalize kernel may begin launching -- its ~4us launch
    // overhead overlaps our ~31us execution. Memory correctness is owned
    // by griddepcontrol.wait in the secondary, NOT by this trigger, so
    // triggering before our stores/atomics is safe.
    asm volatile("griddepcontrol.launch_dependents;" ::: "memory");

    const int g    = blockIdx.x * THREADS + threadIdx.x;   // task id
    const int elem = g / F4;                               // const-div -> mul.hi
    const int f    = g - elem * F4;                        // float4 index in row
    const int lane = threadIdx.x & 31;

    __shared__ float ssum[S];
    if (threadIdx.x < S) ssum[threadIdx.x] = 0.0f;
    __syncthreads();

    float p[S];

    {
        // x row is 12 ints = 48 B, 16B-aligned -> 3 int4 loads.
        // Neighboring lanes share the element -> broadcast/L1 hits.
        const int4* xq = (const int4*)(x + (size_t)elem * XCOLS);
        const int4 q0 = __ldg(&xq[0]);   // x0, x1, c0, c1
        const int4 q1 = __ldg(&xq[1]);   // c2..c5
        const int4 q2 = __ldg(&xq[2]);   // c6..c9
        const int x0 = q0.x;
        const int w[CTX] = {q0.z, q0.w, q1.x, q1.y, q1.z, q1.w, q2.x, q2.y, q2.z, q2.w};

        // 15 fully independent LDG.128s per thread; every lane active.
        float4 tg[CTX];
        #pragma unroll
        for (int j = 0; j < CTX; j++)
            tg[j] = ((const float4*)(Wg + (size_t)w[j] * D))[f];
        float4 ts[S];
        #pragma unroll
        for (int s = 0; s < S; s++)
            ts[s] = ((const float4*)(Ws + ((size_t)x0 * S + s) * D))[f];

        float4 ctx = tg[0];
        #pragma unroll
        for (int j = 1; j < CTX; j++) {
            ctx.x += tg[j].x; ctx.y += tg[j].y;
            ctx.z += tg[j].z; ctx.w += tg[j].w;
        }
        #pragma unroll
        for (int s = 0; s < S; s++)
            p[s] = ts[s].x * ctx.x + ts[s].y * ctx.y
                 + ts[s].z * ctx.z + ts[s].w * ctx.w;
    }

    // warp reduce each sense partial (cross-element mixing is fine: the
    // output sums over the whole batch)
    #pragma unroll
    for (int s = 0; s < S; s++) {
        float v = p[s];
        #pragma unroll
        for (int o = 16; o > 0; o >>= 1)
            v += __shfl_xor_sync(0xFFFFFFFFu, v, o);
        p[s] = v;
    }

    // block combine via shared atomics (8 warps x 5)
    if (lane == 0) {
        #pragma unroll
        for (int s = 0; s < S; s++)
            atomicAdd(&ssum[s], p[s]);
    }
    __syncthreads();

    // one global atomicAdd per block per sense (24000 total to 5 addresses,
    // overlapped with the memory-bound bulk)
    if (threadIdx.x < S)
        atomicAdd(&g_acc[threadIdx.x], ssum[threadIdx.x]);
}

__global__ void finalize_kernel(float* __restrict__ out) {
    // Blocks until the primary grid has completed and its memory (the g_acc
    // atomics) is visible. Launch overhead overlapped via the primary's
    // early griddepcontrol.launch_dependents.
    cudaGridDependencySynchronize();
    if (threadIdx.x < S) {
        float v = g_acc[threadIdx.x];
        out[threadIdx.x] = 1.0f / (1.0f + expf(-v));
        g_acc[threadIdx.x] = 0.0f;   // reset for next call / graph replay
    }
}

extern "C" void kernel_launch(void* const* d_in, const int* in_sizes, int n_in,
                              void* d_out, int out_size) {
    const int*   x  = (const int*)d_in[0];
    const float* Wg = (const float*)d_in[1];
    const float* Ws = (const float*)d_in[2];
    float* out = (float*)d_out;

    sense_main_kernel<<<NBLOCKS, THREADS>>>(x, Wg, Ws);

    cudaLaunchAttribute attrs[1];
    attrs[0].id = cudaLaunchAttributeProgrammaticStreamSerialization;
    attrs[0].val.programmaticStreamSerializationAllowed = 1;

    cudaLaunchConfig_t cfg = {};
    cfg.gridDim = dim3(1, 1, 1);
    cfg.blockDim = dim3(32, 1, 1);
    cfg.dynamicSmemBytes = 0;
    cfg.stream = 0;
    cfg.attrs = attrs;
    cfg.numAttrs = 1;

    cudaLaunchKernelEx(&cfg, finalize_kernel, out);
}